// round 9
// baseline (speedup 1.0000x reference)
#include <cuda_runtime.h>
#include <cuda_fp16.h>
#include <math.h>

#define NPTS 8192
#define DDIM 64
#define NN ((size_t)NPTS * (size_t)NPTS)
#define NITER 50
#define K1 33554432LL   /* 1-based rank of lower middle element (n*n/2) */

#define PBLOCKS 128
#define PTHREADS 1024
#define SPLIT_ROWS 7168        /* rows of K pinned in L2: 7168*16KB = 112 MB (< 126 MB L2) */

// ---- scratch (no cudaMalloc allowed) ----
__device__ float  g_M[67108864];    // 256 MB cost matrix (unnormalized)
__device__ __half g_Kh[67108864];   // 128 MiB scaled Gibbs kernel  K' = e^10 * K
__device__ float g_u[NPTS], g_v[NPTS], g_tmp[NPTS];
__device__ float g_x2[NPTS], g_y2[NPTS];
__device__ unsigned int g_hist0[2048], g_hist1[2048], g_hist2[1024];
__device__ unsigned int g_prefix;
__device__ long long g_k;
__device__ unsigned long long g_cntLE;
__device__ unsigned int g_minGT;
__device__ volatile unsigned int g_barCount;
__device__ volatile unsigned int g_barGen;
__device__ float g_invMedReg;       // 10/med
__device__ float g_lossScale;       // 1/med
__device__ double g_loss;

// ---- L2 residency-controlled 16B load/store ----
__device__ __forceinline__ unsigned long long pol_evict_last() {
    unsigned long long p;
    asm("createpolicy.fractional.L2::evict_last.b64 %0, 1.0;" : "=l"(p));
    return p;
}
__device__ __forceinline__ unsigned long long pol_evict_first() {
    unsigned long long p;
    asm("createpolicy.fractional.L2::evict_first.b64 %0, 1.0;" : "=l"(p));
    return p;
}
__device__ __forceinline__ uint4 ldg_pol(const uint4* p, unsigned long long pol) {
    uint4 v;
    asm("ld.global.L2::cache_hint.v4.u32 {%0,%1,%2,%3}, [%4], %5;"
        : "=r"(v.x), "=r"(v.y), "=r"(v.z), "=r"(v.w) : "l"(p), "l"(pol));
    return v;
}
__device__ __forceinline__ void stg_pol(uint4* p, uint4 v, unsigned long long pol) {
    asm volatile("st.global.L2::cache_hint.v4.u32 [%0], {%1,%2,%3,%4}, %5;"
        :: "l"(p), "r"(v.x), "r"(v.y), "r"(v.z), "r"(v.w), "l"(pol) : "memory");
}

// ---------------- init ----------------
__global__ void k_init() {
    int idx = blockIdx.x * blockDim.x + threadIdx.x;
    if (idx < NPTS) { g_u[idx] = 1.0f / NPTS; g_tmp[idx] = 0.0f; }
    if (idx < 2048) { g_hist0[idx] = 0u; g_hist1[idx] = 0u; }
    if (idx < 1024) g_hist2[idx] = 0u;
    if (idx == 0) {
        g_loss = 0.0;
        g_prefix = 0u;
        g_k = K1;
        g_cntLE = 0ULL;
        g_minGT = 0xFFFFFFFFu;
        g_barCount = 0u;
        g_barGen = 0u;
    }
}

// ---------------- row norms (warp per row) ----------------
__global__ void k_norms(const float* __restrict__ X, const float* __restrict__ Y) {
    int gw = (blockIdx.x * blockDim.x + threadIdx.x) >> 5;
    int lane = threadIdx.x & 31;
    if (gw >= 2 * NPTS) return;
    const float* src = (gw < NPTS) ? X : Y;
    int row = (gw < NPTS) ? gw : gw - NPTS;
    float2 p = ((const float2*)(src + (size_t)row * DDIM))[lane];
    float s = p.x * p.x + p.y * p.y;
    #pragma unroll
    for (int o = 16; o; o >>= 1) s += __shfl_xor_sync(0xFFFFFFFFu, s, o);
    if (lane == 0) { if (gw < NPTS) g_x2[row] = s; else g_y2[row] = s; }
}

// ---------------- M = sq-cdist GEMM + fused level-0 histogram ----------------
__global__ void k_gemm(const float* __restrict__ X, const float* __restrict__ Y) {
    __shared__ float Xs[64][65];
    __shared__ float Ys[64][65];
    __shared__ unsigned int sh[2048];
    int tx = threadIdx.x, ty = threadIdx.y;
    int tid = ty * 16 + tx;
    int lane = tid & 31;
    int i0 = blockIdx.y * 64, j0 = blockIdx.x * 64;

    for (int t = tid; t < 2048; t += 256) sh[t] = 0u;
    for (int t = tid; t < 4096; t += 256) {
        int r = t >> 6, c = t & 63;
        Xs[r][c] = X[(size_t)(i0 + r) * DDIM + c];
        Ys[r][c] = Y[(size_t)(j0 + r) * DDIM + c];
    }
    __syncthreads();

    float acc[4][4] = {};
    #pragma unroll 16
    for (int k = 0; k < 64; k++) {
        float a[4], b[4];
        #pragma unroll
        for (int r = 0; r < 4; r++) a[r] = Xs[ty * 4 + r][k];
        #pragma unroll
        for (int c = 0; c < 4; c++) b[c] = Ys[tx * 4 + c][k];
        #pragma unroll
        for (int r = 0; r < 4; r++)
            #pragma unroll
            for (int c = 0; c < 4; c++) acc[r][c] += a[r] * b[c];
    }

    #pragma unroll
    for (int r = 0; r < 4; r++) {
        int i = i0 + ty * 4 + r;
        float xi = g_x2[i];
        float4 outv;
        float* o = &outv.x;
        #pragma unroll
        for (int c = 0; c < 4; c++) {
            int j = j0 + tx * 4 + c;
            float m = fmaxf(xi + g_y2[j] - 2.0f * acc[r][c], 0.0f);
            o[c] = m;
            unsigned bin = __float_as_uint(m) >> 21;
            unsigned mask = __match_any_sync(0xFFFFFFFFu, bin);
            if (lane == (__ffs(mask) - 1)) atomicAdd(&sh[bin], (unsigned)__popc(mask));
        }
        *(float4*)&g_M[(size_t)i * NPTS + j0 + tx * 4] = outv;
    }
    __syncthreads();
    for (int t = tid; t < 2048; t += 256)
        if (sh[t]) atomicAdd(&g_hist0[t], sh[t]);
}

// ---------------- radix-select scan (block-cooperative, compile-time level) ----------------
template <int LEVEL>
__global__ void k_scan() {
    constexpr int BITS = (LEVEL < 2) ? 11 : 10;
    constexpr int PER = (1 << BITS) >> 8;   // 8 or 4
    __shared__ unsigned int sums[256];
    __shared__ int sh_b;
    __shared__ long long sh_k;
    int t = threadIdx.x;
    const unsigned int* hist = (LEVEL == 0) ? g_hist0 : (LEVEL == 1) ? g_hist1 : g_hist2;
    unsigned int vals[PER];
    unsigned int local = 0;
    #pragma unroll
    for (int i = 0; i < PER; i++) { vals[i] = hist[t * PER + i]; local += vals[i]; }
    sums[t] = local;
    __syncthreads();
    if (t == 0) {
        long long k = g_k, c = 0;
        int b = 0;
        for (; b < 255; b++) {
            long long h = (long long)sums[b];
            if (c + h >= k) break;
            c += h;
        }
        sh_b = b;
        sh_k = k - c;
    }
    __syncthreads();
    if (t == sh_b) {
        long long k2 = sh_k, c = 0;
        int sel = PER - 1;
        #pragma unroll
        for (int i = 0; i < PER - 1; i++) {
            long long h = (long long)vals[i];
            if (sel == PER - 1) {
                if (c + h >= k2) sel = i;
                else c += h;
            }
        }
        g_k = k2 - c;
        g_prefix = (g_prefix << BITS) | (unsigned)(t * PER + sel);
    }
}

// ---------------- filtered histogram passes (levels 1, 2) ----------------
template <int LEVEL>
__global__ void k_hist() {
    constexpr int NB = (LEVEL == 1) ? 2048 : 1024;
    __shared__ unsigned int sh[NB];
    int tid = threadIdx.x;
    for (int t = tid; t < NB; t += blockDim.x) sh[t] = 0u;
    __syncthreads();
    unsigned pref = g_prefix;
    size_t stride = (size_t)gridDim.x * blockDim.x;
    for (size_t idx = (size_t)blockIdx.x * blockDim.x + tid; idx < NN; idx += stride) {
        unsigned bv = __float_as_uint(g_M[idx]);
        if (LEVEL == 1) {
            if ((bv >> 21) == pref) atomicAdd(&sh[(bv >> 10) & 2047u], 1u);
        } else {
            if ((bv >> 10) == pref) atomicAdd(&sh[bv & 1023u], 1u);
        }
    }
    __syncthreads();
    unsigned int* dst = (LEVEL == 1) ? g_hist1 : g_hist2;
    for (int t = tid; t < NB; t += blockDim.x)
        if (sh[t]) atomicAdd(&dst[t], sh[t]);
}

// ---------------- count <= v1, min of elements > v1 ----------------
__global__ void k_cntmin() {
    unsigned v1 = g_prefix;
    unsigned long long cnt = 0ULL;
    unsigned mn = 0xFFFFFFFFu;
    size_t stride = (size_t)gridDim.x * blockDim.x;
    for (size_t idx = (size_t)blockIdx.x * blockDim.x + threadIdx.x; idx < NN; idx += stride) {
        unsigned bv = __float_as_uint(g_M[idx]);
        if (bv <= v1) cnt++;
        else mn = min(mn, bv);
    }
    #pragma unroll
    for (int o = 16; o; o >>= 1) {
        cnt += __shfl_xor_sync(0xFFFFFFFFu, cnt, o);
        mn = min(mn, __shfl_xor_sync(0xFFFFFFFFu, mn, o));
    }
    if ((threadIdx.x & 31) == 0) {
        atomicAdd(&g_cntLE, cnt);
        atomicMin(&g_minGT, mn);
    }
}

// ---------------- median finalize ----------------
__global__ void k_med() {
    float v1 = __uint_as_float(g_prefix);
    float v2 = (g_cntLE >= (unsigned long long)(K1 + 1)) ? v1 : __uint_as_float(g_minGT);
    float med = 0.5f * (v1 + v2);
    if (med > 0.0f) {
        g_invMedReg = 10.0f / med;   // SREG = 0.1
        g_lossScale = 1.0f / med;
    } else {
        g_invMedReg = 10.0f;
        g_lossScale = 1.0f;
    }
}

// ---------------- K' = e^10 * exp(-M * invMedReg)  (fp16, L2-pin prewarm) ----------------
__global__ void k_gibbs() {
    float inv = g_invMedReg;
    unsigned long long pl = pol_evict_last();
    unsigned long long pf = pol_evict_first();
    size_t stride = (size_t)gridDim.x * blockDim.x;
    const float4* Mi = (const float4*)g_M;
    uint4* Ko = (uint4*)g_Kh;
    const size_t qSplit = (size_t)SPLIT_ROWS * (NPTS / 8);
    for (size_t q = (size_t)blockIdx.x * blockDim.x + threadIdx.x; q < NN / 8; q += stride) {
        float4 m0 = Mi[2 * q];
        float4 m1 = Mi[2 * q + 1];
        __half2 h0 = __floats2half2_rn(__expf(10.0f - m0.x * inv), __expf(10.0f - m0.y * inv));
        __half2 h1 = __floats2half2_rn(__expf(10.0f - m0.z * inv), __expf(10.0f - m0.w * inv));
        __half2 h2 = __floats2half2_rn(__expf(10.0f - m1.x * inv), __expf(10.0f - m1.y * inv));
        __half2 h3 = __floats2half2_rn(__expf(10.0f - m1.z * inv), __expf(10.0f - m1.w * inv));
        uint4 o;
        o.x = *(unsigned int*)&h0;
        o.y = *(unsigned int*)&h1;
        o.z = *(unsigned int*)&h2;
        o.w = *(unsigned int*)&h3;
        stg_pol(Ko + q, o, (q < qSplit) ? pl : pf);
    }
}

// ---------------- persistent Sinkhorn loop ----------------
// 128 blocks x 1024 threads; all blocks co-resident (grid <= #SMs, 1 block/SM),
// so a spin grid-barrier is safe. Sense-reversing generation barrier.
__device__ __forceinline__ void grid_sync() {
    __syncthreads();
    if (threadIdx.x == 0) {
        __threadfence();
        unsigned gen = g_barGen;
        if (atomicAdd((unsigned int*)&g_barCount, 1u) == PBLOCKS - 1) {
            g_barCount = 0u;
            __threadfence();
            g_barGen = gen + 1u;
        } else {
            while (g_barGen == gen) { __nanosleep(32); }
        }
        __threadfence();
    }
    __syncthreads();
}

__global__ void __launch_bounds__(PTHREADS, 1) k_sink() {
    int tid = threadIdx.x;
    int bid = blockIdx.x;
    int lane = tid & 31;
    int warp = tid >> 5;
    unsigned long long pl = pol_evict_last();
    unsigned long long pf = pol_evict_first();
    __shared__ float us[64];

    for (int it = 0; it < NITER; it++) {
        // ---- Phase A: tmp_j = sum_i K'_ij u_i  (block owns 64 rows, thread owns uint4-col tid)
        int r0 = bid * 64;
        if (tid < 64) us[tid] = g_u[r0 + tid];
        __syncthreads();
        {
            unsigned long long pol = (r0 < SPLIT_ROWS) ? pl : pf;
            const uint4* Kb = (const uint4*)(g_Kh + (size_t)r0 * NPTS) + tid;
            float a0 = 0.f, a1 = 0.f, a2 = 0.f, a3 = 0.f, a4 = 0.f, a5 = 0.f, a6 = 0.f, a7 = 0.f;
            #pragma unroll 8
            for (int r = 0; r < 64; r++) {
                float uu = us[r];
                uint4 kv = ldg_pol(Kb + (size_t)r * (NPTS / 8), pol);
                float2 f0 = __half22float2(*(__half2*)&kv.x);
                float2 f1 = __half22float2(*(__half2*)&kv.y);
                float2 f2 = __half22float2(*(__half2*)&kv.z);
                float2 f3 = __half22float2(*(__half2*)&kv.w);
                a0 += f0.x * uu; a1 += f0.y * uu;
                a2 += f1.x * uu; a3 += f1.y * uu;
                a4 += f2.x * uu; a5 += f2.y * uu;
                a6 += f3.x * uu; a7 += f3.y * uu;
            }
            int j = tid * 8;
            atomicAdd(&g_tmp[j + 0], a0); atomicAdd(&g_tmp[j + 1], a1);
            atomicAdd(&g_tmp[j + 2], a2); atomicAdd(&g_tmp[j + 3], a3);
            atomicAdd(&g_tmp[j + 4], a4); atomicAdd(&g_tmp[j + 5], a5);
            atomicAdd(&g_tmp[j + 6], a6); atomicAdd(&g_tmp[j + 7], a7);
        }
        grid_sync();

        // ---- Phase B: v = nu / tmp ; tmp = 0   (first 8192 global threads)
        {
            int g = bid * PTHREADS + tid;
            if (g < NPTS) {
                g_v[g] = (1.0f / NPTS) / g_tmp[g];
                g_tmp[g] = 0.0f;
            }
        }
        grid_sync();

        // ---- Phase C: u_i = mu / sum_j K'_ij v_j  (4096 warps x exactly 2 rows)
        {
            int gw = bid * 32 + warp;     // 0..4095
            const float4* V = (const float4*)g_v;
            #pragma unroll
            for (int rr = 0; rr < 2; rr++) {
                int row = gw * 2 + rr;
                unsigned long long pol = (row < SPLIT_ROWS) ? pl : pf;
                const uint4* Kr = (const uint4*)(g_Kh + (size_t)row * NPTS);
                float s0 = 0.f, s1 = 0.f, s2 = 0.f, s3 = 0.f;
                #pragma unroll 8
                for (int c = lane; c < NPTS / 8; c += 32) {
                    uint4 kv = ldg_pol(Kr + c, pol);
                    float4 va = V[2 * c], vb = V[2 * c + 1];
                    float2 f0 = __half22float2(*(__half2*)&kv.x);
                    float2 f1 = __half22float2(*(__half2*)&kv.y);
                    float2 f2 = __half22float2(*(__half2*)&kv.z);
                    float2 f3 = __half22float2(*(__half2*)&kv.w);
                    s0 += f0.x * va.x + f0.y * va.y;
                    s1 += f1.x * va.z + f1.y * va.w;
                    s2 += f2.x * vb.x + f2.y * vb.y;
                    s3 += f3.x * vb.z + f3.y * vb.w;
                }
                float s = (s0 + s1) + (s2 + s3);
                #pragma unroll
                for (int o = 16; o; o >>= 1) s += __shfl_xor_sync(0xFFFFFFFFu, s, o);
                if (lane == 0) g_u[row] = (1.0f / NPTS) / s;
            }
        }
        grid_sync();
    }
}

// ---------------- loss = sum u_i K'_ij v'_j M_ij ----------------
__global__ void k_loss() {
    double acc = 0.0;
    size_t stride = (size_t)gridDim.x * blockDim.x;
    const uint4* Kp = (const uint4*)g_Kh;
    const float4* Mp = (const float4*)g_M;
    const float4* Vp = (const float4*)g_v;
    for (size_t q = (size_t)blockIdx.x * blockDim.x + threadIdx.x; q < NN / 8; q += stride) {
        size_t i = q >> 10;          // q*8 / 8192
        int j8 = (int)(q & 1023);
        uint4 kq = Kp[q];
        float4 m0 = Mp[2 * q], m1 = Mp[2 * q + 1];
        float4 va = Vp[2 * j8], vb = Vp[2 * j8 + 1];
        float2 f0 = __half22float2(*(__half2*)&kq.x);
        float2 f1 = __half22float2(*(__half2*)&kq.y);
        float2 f2 = __half22float2(*(__half2*)&kq.z);
        float2 f3 = __half22float2(*(__half2*)&kq.w);
        float ui = g_u[i];
        float t = f0.x * va.x * m0.x + f0.y * va.y * m0.y
                + f1.x * va.z * m0.z + f1.y * va.w * m0.w
                + f2.x * vb.x * m1.x + f2.y * vb.y * m1.y
                + f3.x * vb.z * m1.z + f3.y * vb.w * m1.w;
        acc += (double)ui * (double)t;
    }
    #pragma unroll
    for (int o = 16; o; o >>= 1) acc += __shfl_xor_sync(0xFFFFFFFFu, acc, o);
    __shared__ double sh[8];
    int warp = threadIdx.x >> 5, lane = threadIdx.x & 31;
    if (lane == 0) sh[warp] = acc;
    __syncthreads();
    if (threadIdx.x == 0) {
        double s = 0.0;
        #pragma unroll
        for (int w = 0; w < 8; w++) s += sh[w];
        atomicAdd(&g_loss, s);
    }
}

__global__ void k_out(float* out) {
    out[0] = (float)(g_loss * (double)g_lossScale);
}

extern "C" void kernel_launch(void* const* d_in, const int* in_sizes, int n_in,
                              void* d_out, int out_size) {
    const float* X = (const float*)d_in[0];
    const float* Y = (const float*)d_in[1];

    k_init<<<32, 256>>>();
    k_norms<<<2048, 256>>>(X, Y);
    k_gemm<<<dim3(128, 128), dim3(16, 16)>>>(X, Y);
    k_scan<0><<<1, 256>>>();
    k_hist<1><<<2048, 256>>>();
    k_scan<1><<<1, 256>>>();
    k_hist<2><<<2048, 256>>>();
    k_scan<2><<<1, 256>>>();
    k_cntmin<<<2048, 256>>>();
    k_med<<<1, 1>>>();
    k_gibbs<<<2048, 256>>>();

    k_sink<<<PBLOCKS, PTHREADS>>>();

    k_loss<<<1024, 256>>>();
    k_out<<<1, 1>>>((float*)d_out);
}

// round 11
// speedup vs baseline: 1.2742x; 1.2742x over previous
#include <cuda_runtime.h>
#include <math.h>

#define NPTS 8192
#define DDIM 64
#define NN ((size_t)NPTS * (size_t)NPTS)
#define NITER 50
#define K1 33554432LL   /* 1-based rank of lower middle element (n*n/2) */

#define PBLOCKS 128
#define PTHREADS 1024

// fp8(e4m3, sign=0) -> f32 * 2^-120 via integer shift (subnormals exact)
#define F8(w,k) __uint_as_float((((w) >> (8*(k))) & 0x7Fu) << 20)

// ---- scratch (no cudaMalloc allowed) ----
__device__ float g_M[67108864];          // 256 MB cost matrix (unnormalized)
__device__ unsigned char g_K8[67108864]; // 64 MB e4m3 kernel: fits in L2!
__device__ float g_v[NPTS];              // v * 2^120
__device__ float g_tmp[NPTS], g_tmp2[NPTS];
__device__ float g_x2[NPTS], g_y2[NPTS];
__device__ unsigned int g_hist0[2048], g_hist1[2048], g_hist2[1024];
__device__ unsigned int g_prefix;
__device__ long long g_k;
__device__ unsigned long long g_cntLE;
__device__ unsigned int g_minGT;
__device__ unsigned int g_minAll;
__device__ volatile unsigned int g_barCount;
__device__ volatile unsigned int g_barGen;
__device__ float g_invMedReg;   // 10/med
__device__ float g_expS;        // ln(400) + Mmin*10/med
__device__ float g_lossScale;   // 1/med
__device__ double g_loss;

// ---------------- init ----------------
__global__ void k_init() {
    int idx = blockIdx.x * blockDim.x + threadIdx.x;
    if (idx < NPTS) { g_tmp[idx] = 0.0f; g_tmp2[idx] = 1.0f; }  // tmp2=1 => u0 = mu = 1/N
    if (idx < 2048) { g_hist0[idx] = 0u; g_hist1[idx] = 0u; }
    if (idx < 1024) g_hist2[idx] = 0u;
    if (idx == 0) {
        g_loss = 0.0;
        g_prefix = 0u;
        g_k = K1;
        g_cntLE = 0ULL;
        g_minGT = 0xFFFFFFFFu;
        g_minAll = 0xFFFFFFFFu;
        g_barCount = 0u;
        g_barGen = 0u;
    }
}

// ---------------- row norms (warp per row) ----------------
__global__ void k_norms(const float* __restrict__ X, const float* __restrict__ Y) {
    int gw = (blockIdx.x * blockDim.x + threadIdx.x) >> 5;
    int lane = threadIdx.x & 31;
    if (gw >= 2 * NPTS) return;
    const float* src = (gw < NPTS) ? X : Y;
    int row = (gw < NPTS) ? gw : gw - NPTS;
    float2 p = ((const float2*)(src + (size_t)row * DDIM))[lane];
    float s = p.x * p.x + p.y * p.y;
    #pragma unroll
    for (int o = 16; o; o >>= 1) s += __shfl_xor_sync(0xFFFFFFFFu, s, o);
    if (lane == 0) { if (gw < NPTS) g_x2[row] = s; else g_y2[row] = s; }
}

// ---------------- M = sq-cdist GEMM + fused level-0 histogram + global min ----------------
__global__ void k_gemm(const float* __restrict__ X, const float* __restrict__ Y) {
    __shared__ float Xs[64][65];
    __shared__ float Ys[64][65];
    __shared__ unsigned int sh[2048];
    int tx = threadIdx.x, ty = threadIdx.y;
    int tid = ty * 16 + tx;
    int lane = tid & 31;
    int i0 = blockIdx.y * 64, j0 = blockIdx.x * 64;

    for (int t = tid; t < 2048; t += 256) sh[t] = 0u;
    for (int t = tid; t < 4096; t += 256) {
        int r = t >> 6, c = t & 63;
        Xs[r][c] = X[(size_t)(i0 + r) * DDIM + c];
        Ys[r][c] = Y[(size_t)(j0 + r) * DDIM + c];
    }
    __syncthreads();

    float acc[4][4] = {};
    #pragma unroll 16
    for (int k = 0; k < 64; k++) {
        float a[4], b[4];
        #pragma unroll
        for (int r = 0; r < 4; r++) a[r] = Xs[ty * 4 + r][k];
        #pragma unroll
        for (int c = 0; c < 4; c++) b[c] = Ys[tx * 4 + c][k];
        #pragma unroll
        for (int r = 0; r < 4; r++)
            #pragma unroll
            for (int c = 0; c < 4; c++) acc[r][c] += a[r] * b[c];
    }

    float lmin = 3.4e38f;
    #pragma unroll
    for (int r = 0; r < 4; r++) {
        int i = i0 + ty * 4 + r;
        float xi = g_x2[i];
        float4 outv;
        float* o = &outv.x;
        #pragma unroll
        for (int c = 0; c < 4; c++) {
            int j = j0 + tx * 4 + c;
            float m = fmaxf(xi + g_y2[j] - 2.0f * acc[r][c], 0.0f);
            o[c] = m;
            lmin = fminf(lmin, m);
            unsigned bin = __float_as_uint(m) >> 21;
            unsigned mask = __match_any_sync(0xFFFFFFFFu, bin);
            if (lane == (__ffs(mask) - 1)) atomicAdd(&sh[bin], (unsigned)__popc(mask));
        }
        *(float4*)&g_M[(size_t)i * NPTS + j0 + tx * 4] = outv;
    }
    unsigned lm = __float_as_uint(lmin);
    #pragma unroll
    for (int o = 16; o; o >>= 1) lm = min(lm, __shfl_xor_sync(0xFFFFFFFFu, lm, o));
    if (lane == 0) atomicMin(&g_minAll, lm);
    __syncthreads();
    for (int t = tid; t < 2048; t += 256)
        if (sh[t]) atomicAdd(&g_hist0[t], sh[t]);
}

// ---------------- radix-select scan (block-cooperative, compile-time level) ----------------
template <int LEVEL>
__global__ void k_scan() {
    constexpr int BITS = (LEVEL < 2) ? 11 : 10;
    constexpr int PER = (1 << BITS) >> 8;   // 8 or 4
    __shared__ unsigned int sums[256];
    __shared__ int sh_b;
    __shared__ long long sh_k;
    int t = threadIdx.x;
    const unsigned int* hist = (LEVEL == 0) ? g_hist0 : (LEVEL == 1) ? g_hist1 : g_hist2;
    unsigned int vals[PER];
    unsigned int local = 0;
    #pragma unroll
    for (int i = 0; i < PER; i++) { vals[i] = hist[t * PER + i]; local += vals[i]; }
    sums[t] = local;
    __syncthreads();
    if (t == 0) {
        long long k = g_k, c = 0;
        int b = 0;
        for (; b < 255; b++) {
            long long h = (long long)sums[b];
            if (c + h >= k) break;
            c += h;
        }
        sh_b = b;
        sh_k = k - c;
    }
    __syncthreads();
    if (t == sh_b) {
        long long k2 = sh_k, c = 0;
        int sel = PER - 1;
        #pragma unroll
        for (int i = 0; i < PER - 1; i++) {
            long long h = (long long)vals[i];
            if (sel == PER - 1) {
                if (c + h >= k2) sel = i;
                else c += h;
            }
        }
        g_k = k2 - c;
        g_prefix = (g_prefix << BITS) | (unsigned)(t * PER + sel);
    }
}

// ---------------- filtered histogram passes (levels 1, 2) ----------------
template <int LEVEL>
__global__ void k_hist() {
    constexpr int NB = (LEVEL == 1) ? 2048 : 1024;
    __shared__ unsigned int sh[NB];
    int tid = threadIdx.x;
    for (int t = tid; t < NB; t += blockDim.x) sh[t] = 0u;
    __syncthreads();
    unsigned pref = g_prefix;
    size_t stride = (size_t)gridDim.x * blockDim.x;
    for (size_t idx = (size_t)blockIdx.x * blockDim.x + tid; idx < NN; idx += stride) {
        unsigned bv = __float_as_uint(g_M[idx]);
        if (LEVEL == 1) {
            if ((bv >> 21) == pref) atomicAdd(&sh[(bv >> 10) & 2047u], 1u);
        } else {
            if ((bv >> 10) == pref) atomicAdd(&sh[bv & 1023u], 1u);
        }
    }
    __syncthreads();
    unsigned int* dst = (LEVEL == 1) ? g_hist1 : g_hist2;
    for (int t = tid; t < NB; t += blockDim.x)
        if (sh[t]) atomicAdd(&dst[t], sh[t]);
}

// ---------------- count <= v1, min of elements > v1 ----------------
__global__ void k_cntmin() {
    unsigned v1 = g_prefix;
    unsigned long long cnt = 0ULL;
    unsigned mn = 0xFFFFFFFFu;
    size_t stride = (size_t)gridDim.x * blockDim.x;
    for (size_t idx = (size_t)blockIdx.x * blockDim.x + threadIdx.x; idx < NN; idx += stride) {
        unsigned bv = __float_as_uint(g_M[idx]);
        if (bv <= v1) cnt++;
        else mn = min(mn, bv);
    }
    #pragma unroll
    for (int o = 16; o; o >>= 1) {
        cnt += __shfl_xor_sync(0xFFFFFFFFu, cnt, o);
        mn = min(mn, __shfl_xor_sync(0xFFFFFFFFu, mn, o));
    }
    if ((threadIdx.x & 31) == 0) {
        atomicAdd(&g_cntLE, cnt);
        atomicMin(&g_minGT, mn);
    }
}

// ---------------- median finalize ----------------
__global__ void k_med() {
    float v1 = __uint_as_float(g_prefix);
    float v2 = (g_cntLE >= (unsigned long long)(K1 + 1)) ? v1 : __uint_as_float(g_minGT);
    float med = 0.5f * (v1 + v2);
    float inv;
    if (med > 0.0f) {
        inv = 10.0f / med;
        g_lossScale = 1.0f / med;
    } else {
        inv = 10.0f;
        g_lossScale = 1.0f;
    }
    g_invMedReg = inv;
    // scale so max K8 entry ~ 400 (e4m3 max 448): s = ln(400) + Mmin*inv
    g_expS = 5.9915f + __uint_as_float(g_minAll) * inv;
}

// ---------------- K8 = e4m3( exp(s - M*10/med) ) ----------------
__global__ void k_gibbs() {
    float inv = g_invMedReg;
    float s = g_expS;
    size_t stride = (size_t)gridDim.x * blockDim.x;
    const float4* Mi = (const float4*)g_M;
    uint4* Ko = (uint4*)g_K8;
    for (size_t q = (size_t)blockIdx.x * blockDim.x + threadIdx.x; q < NN / 16; q += stride) {
        unsigned wds[4];
        #pragma unroll
        for (int h = 0; h < 4; h++) {
            float4 m = Mi[4 * q + h];
            float e0 = __expf(s - m.x * inv);
            float e1 = __expf(s - m.y * inv);
            float e2 = __expf(s - m.z * inv);
            float e3 = __expf(s - m.w * inv);
            unsigned short lo, hi;
            asm("cvt.rn.satfinite.e4m3x2.f32 %0, %1, %2;" : "=h"(lo) : "f"(e1), "f"(e0));
            asm("cvt.rn.satfinite.e4m3x2.f32 %0, %1, %2;" : "=h"(hi) : "f"(e3), "f"(e2));
            wds[h] = (unsigned)lo | ((unsigned)hi << 16);
        }
        Ko[q] = make_uint4(wds[0], wds[1], wds[2], wds[3]);
    }
}

// ---------------- persistent Sinkhorn loop (K8 L2-resident) ----------------
__device__ __forceinline__ void grid_sync() {
    __syncthreads();
    if (threadIdx.x == 0) {
        __threadfence();
        unsigned gen = g_barGen;
        if (atomicAdd((unsigned int*)&g_barCount, 1u) == PBLOCKS - 1) {
            g_barCount = 0u;
            __threadfence();
            g_barGen = gen + 1u;
        } else {
            while (g_barGen == gen) { __nanosleep(32); }
        }
        __threadfence();
    }
    __syncthreads();
}

__global__ void __launch_bounds__(PTHREADS, 1) k_sink() {
    int tid = threadIdx.x;
    int bid = blockIdx.x;
    int lane = tid & 31;
    int warp = tid >> 5;
    __shared__ float us[64];      // u * 2^120 for this block's 64 rows
    __shared__ float sAcc[8192];  // cross-half column partials

    for (int it = 0; it < NITER; it++) {
        // ---- Phase A: tmp_j = sum_i K8_ij * u_i ; u_i = mu / tmp2_i on the fly
        int r0 = bid * 64;
        if (tid < 64) us[tid] = (1.0f / NPTS) / g_tmp2[r0 + tid] * 0x1p120f;
        __syncthreads();
        {
            int c = tid & 511;              // uint4 column group (16 elems)
            int rbase = (tid >> 9) * 32;    // 0 or 32
            const uint4* Kb = (const uint4*)(g_K8 + (size_t)(r0 + rbase) * NPTS) + c;
            float acc[16];
            #pragma unroll
            for (int e = 0; e < 16; e++) acc[e] = 0.f;
            #pragma unroll 4
            for (int r = 0; r < 32; r++) {
                float uu = us[rbase + r];
                uint4 kv = Kb[(size_t)r * (NPTS / 16)];
                unsigned w0 = kv.x, w1 = kv.y, w2 = kv.z, w3 = kv.w;
                acc[0]  += F8(w0,0)*uu; acc[1]  += F8(w0,1)*uu; acc[2]  += F8(w0,2)*uu; acc[3]  += F8(w0,3)*uu;
                acc[4]  += F8(w1,0)*uu; acc[5]  += F8(w1,1)*uu; acc[6]  += F8(w1,2)*uu; acc[7]  += F8(w1,3)*uu;
                acc[8]  += F8(w2,0)*uu; acc[9]  += F8(w2,1)*uu; acc[10] += F8(w2,2)*uu; acc[11] += F8(w2,3)*uu;
                acc[12] += F8(w3,0)*uu; acc[13] += F8(w3,1)*uu; acc[14] += F8(w3,2)*uu; acc[15] += F8(w3,3)*uu;
            }
            if (tid >= 512) {
                #pragma unroll
                for (int e = 0; e < 16; e++) sAcc[e * 512 + c] = acc[e];
            }
            __syncthreads();
            if (tid < 512) {
                #pragma unroll
                for (int e = 0; e < 16; e++)
                    atomicAdd(&g_tmp[c * 16 + e], acc[e] + sAcc[e * 512 + c]);
            }
        }
        grid_sync();

        // ---- Phase B: v' = (nu/tmp)*2^120 ; tmp = 0 ; tmp2 = 0
        {
            int g = bid * PTHREADS + tid;
            if (g < NPTS) {
                g_v[g] = (1.0f / NPTS) / g_tmp[g] * 0x1p120f;
                g_tmp[g] = 0.0f;
                g_tmp2[g] = 0.0f;
            }
        }
        grid_sync();

        // ---- Phase C: tmp2_i = sum_j K8_ij v'_j (column-strip warps, v in regs)
        {
            int gw = bid * 32 + warp;       // 0..4095
            int s = gw & 15;                // column strip (512 cols)
            int row0 = (gw >> 4) * 32;      // 32-row block
            float vr[16];
            const float4* V4 = (const float4*)g_v + (s * 128 + lane * 4);
            #pragma unroll
            for (int h = 0; h < 4; h++) {
                float4 t = V4[h];
                vr[h*4] = t.x; vr[h*4+1] = t.y; vr[h*4+2] = t.z; vr[h*4+3] = t.w;
            }
            const uint4* Kb = (const uint4*)g_K8 + (size_t)row0 * (NPTS / 16) + s * 32 + lane;
            #pragma unroll 4
            for (int r = 0; r < 32; r++) {
                uint4 kv = Kb[(size_t)r * (NPTS / 16)];
                unsigned w0 = kv.x, w1 = kv.y, w2 = kv.z, w3 = kv.w;
                float sm;
                sm  = F8(w0,0)*vr[0]  + F8(w0,1)*vr[1]  + F8(w0,2)*vr[2]  + F8(w0,3)*vr[3];
                sm += F8(w1,0)*vr[4]  + F8(w1,1)*vr[5]  + F8(w1,2)*vr[6]  + F8(w1,3)*vr[7];
                sm += F8(w2,0)*vr[8]  + F8(w2,1)*vr[9]  + F8(w2,2)*vr[10] + F8(w2,3)*vr[11];
                sm += F8(w3,0)*vr[12] + F8(w3,1)*vr[13] + F8(w3,2)*vr[14] + F8(w3,3)*vr[15];
                #pragma unroll
                for (int o = 16; o; o >>= 1) sm += __shfl_xor_sync(0xFFFFFFFFu, sm, o);
                if (lane == 0) atomicAdd(&g_tmp2[row0 + r], sm);
            }
        }
        grid_sync();
    }
}

// ---------------- loss = sum u_i K8_ij v_j M_ij  (u = mu/tmp2) ----------------
__global__ void k_loss() {
    double acc = 0.0;
    size_t stride = (size_t)gridDim.x * blockDim.x;
    const uint4* Kp = (const uint4*)g_K8;
    const float4* Mp = (const float4*)g_M;
    const float4* Vp = (const float4*)g_v;
    for (size_t q = (size_t)blockIdx.x * blockDim.x + threadIdx.x; q < NN / 16; q += stride) {
        size_t i = q >> 9;             // q*16 / 8192
        int j16 = (int)(q & 511);
        uint4 kq = Kp[q];
        unsigned w0 = kq.x, w1 = kq.y, w2 = kq.z, w3 = kq.w;
        float ui = (1.0f / NPTS) / g_tmp2[i];
        float4 m0 = Mp[4*q+0], m1 = Mp[4*q+1], m2 = Mp[4*q+2], m3 = Mp[4*q+3];
        float4 v0 = Vp[4*j16+0], v1 = Vp[4*j16+1], v2 = Vp[4*j16+2], v3 = Vp[4*j16+3];
        float t;
        t  = F8(w0,0)*v0.x*m0.x + F8(w0,1)*v0.y*m0.y + F8(w0,2)*v0.z*m0.z + F8(w0,3)*v0.w*m0.w;
        t += F8(w1,0)*v1.x*m1.x + F8(w1,1)*v1.y*m1.y + F8(w1,2)*v1.z*m1.z + F8(w1,3)*v1.w*m1.w;
        t += F8(w2,0)*v2.x*m2.x + F8(w2,1)*v2.y*m2.y + F8(w2,2)*v2.z*m2.z + F8(w2,3)*v2.w*m2.w;
        t += F8(w3,0)*v3.x*m3.x + F8(w3,1)*v3.y*m3.y + F8(w3,2)*v3.z*m3.z + F8(w3,3)*v3.w*m3.w;
        acc += (double)ui * (double)t;
    }
    #pragma unroll
    for (int o = 16; o; o >>= 1) acc += __shfl_xor_sync(0xFFFFFFFFu, acc, o);
    __shared__ double sh[8];
    int warp = threadIdx.x >> 5, lane = threadIdx.x & 31;
    if (lane == 0) sh[warp] = acc;
    __syncthreads();
    if (threadIdx.x == 0) {
        double s = 0.0;
        #pragma unroll
        for (int w = 0; w < 8; w++) s += sh[w];
        atomicAdd(&g_loss, s);
    }
}

__global__ void k_out(float* out) {
    out[0] = (float)(g_loss * (double)g_lossScale);
}

extern "C" void kernel_launch(void* const* d_in, const int* in_sizes, int n_in,
                              void* d_out, int out_size) {
    const float* X = (const float*)d_in[0];
    const float* Y = (const float*)d_in[1];

    k_init<<<32, 256>>>();
    k_norms<<<2048, 256>>>(X, Y);
    k_gemm<<<dim3(128, 128), dim3(16, 16)>>>(X, Y);
    k_scan<0><<<1, 256>>>();
    k_hist<1><<<2048, 256>>>();
    k_scan<1><<<1, 256>>>();
    k_hist<2><<<2048, 256>>>();
    k_scan<2><<<1, 256>>>();
    k_cntmin<<<2048, 256>>>();
    k_med<<<1, 1>>>();
    k_gibbs<<<2048, 256>>>();

    k_sink<<<PBLOCKS, PTHREADS>>>();

    k_loss<<<1024, 256>>>();
    k_out<<<1, 1>>>((float*)d_out);
}